// round 9
// baseline (speedup 1.0000x reference)
#include <cuda_runtime.h>

// CostVolume1D: out[n,d,h,w] = (1/C) * sum_c f1[n,c,h,w] * f2pad[n,c,h,w+d-4]
// f1,f2: [4,128,192,640] fp32. Shuffle-halo float4 kernel (R7 compute,
// unroll 4, no cache hints, no reg cap) with TPB=96 -> 1280 CTAs ->
// 8.65 CTAs/SM for finer wave balance (was 6.49 @ TPB=128, ~8% imbalance).
// VW=160 is a multiple of 32, so warps still cover 32 consecutive v of one
// row and the shuffle halo stays valid.

#define Nn   4
#define Cc   128
#define Hh   192
#define Ww   640
#define Dd   4
#define NS   (2*Dd + 1)       // 9
#define TPB  96
#define VW   (Ww / 4)         // 160 float4 per row
#define CH4  (Hh * VW)        // channel stride in float4 units (30720)

__global__ __launch_bounds__(TPB)
void costvol1d_kernel(const float4* __restrict__ f1,
                      const float4* __restrict__ f2,
                      float* __restrict__ out)
{
    const int gid  = blockIdx.x * TPB + threadIdx.x;  // 0 .. N*H*VW-1
    const int v    = gid % VW;         // float4 index within row
    const int row  = gid / VW;         // n*Hh + h
    const int n    = row / Hh;
    const int h    = row % Hh;
    const int lane = threadIdx.x & 31;

    // Edge-lane predicated load: lane 0 fetches f2[o-1] (if v>0),
    // lane 31 fetches f2[o+1] (if v<VW-1). Other lanes never load it.
    const bool evalid = (lane == 0) ? (v > 0)
                      : (lane == 31) ? (v < VW - 1) : false;
    const int  eoff   = (lane == 0) ? -1 : 1;

    // 32-bit indexing: max index = 4*128*192*160 = 15,728,640 < 2^31.
    const int base = (n * Cc * Hh + h) * VW + v;   // channel 0

    float acc[NS * 4];
    #pragma unroll
    for (int i = 0; i < NS * 4; i++) acc[i] = 0.0f;

    const float4 z4 = make_float4(0.f, 0.f, 0.f, 0.f);

    #pragma unroll 4
    for (int c = 0; c < Cc; c++) {
        const int o = base + c * CH4;

        const float4 a  = f1[o];
        const float4 c0 = f2[o];
        const float4 e  = evalid ? f2[o + eoff] : z4;

        // Neighbor float4s via warp shuffle of c0 (warp = 32 consecutive v).
        float4 cm, cp;
        cm.x = __shfl_up_sync(0xffffffffu, c0.x, 1);
        cm.y = __shfl_up_sync(0xffffffffu, c0.y, 1);
        cm.z = __shfl_up_sync(0xffffffffu, c0.z, 1);
        cm.w = __shfl_up_sync(0xffffffffu, c0.w, 1);
        cp.x = __shfl_down_sync(0xffffffffu, c0.x, 1);
        cp.y = __shfl_down_sync(0xffffffffu, c0.y, 1);
        cp.z = __shfl_down_sync(0xffffffffu, c0.z, 1);
        cp.w = __shfl_down_sync(0xffffffffu, c0.w, 1);
        if (lane == 0)  cm = e;   // left edge of warp's 32-v span
        if (lane == 31) cp = e;   // right edge

        // window win[k] = f2pad[w-4+k], k=0..11
        float win[12];
        win[0] = cm.x; win[1] = cm.y; win[2]  = cm.z; win[3]  = cm.w;
        win[4] = c0.x; win[5] = c0.y; win[6]  = c0.z; win[7]  = c0.w;
        win[8] = cp.x; win[9] = cp.y; win[10] = cp.z; win[11] = cp.w;

        float av[4];
        av[0] = a.x; av[1] = a.y; av[2] = a.z; av[3] = a.w;

        #pragma unroll
        for (int d = 0; d < NS; d++) {
            #pragma unroll
            for (int j = 0; j < 4; j++) {
                acc[d * 4 + j] = fmaf(av[j], win[j + d], acc[d * 4 + j]);
            }
        }
    }

    // Epilogue: channel mean, float4 stores. out[n][d][h][w..w+3]
    const float inv = 1.0f / (float)Cc;
    float4* o4 = (float4*)out;
    #pragma unroll
    for (int d = 0; d < NS; d++) {
        float4 o;
        o.x = acc[d * 4 + 0] * inv;
        o.y = acc[d * 4 + 1] * inv;
        o.z = acc[d * 4 + 2] * inv;
        o.w = acc[d * 4 + 3] * inv;
        o4[((n * NS + d) * Hh + h) * VW + v] = o;
    }
}

extern "C" void kernel_launch(void* const* d_in, const int* in_sizes, int n_in,
                              void* d_out, int out_size)
{
    const float4* f1 = (const float4*)d_in[0];
    const float4* f2 = (const float4*)d_in[1];
    float* out = (float*)d_out;
    (void)in_sizes; (void)n_in; (void)out_size;

    const int total = Nn * Hh * VW;          // 122880 threads, 1 float4 each
    dim3 grid(total / TPB);                  // 1280 blocks of 96
    dim3 block(TPB);
    costvol1d_kernel<<<grid, block>>>(f1, f2, out);
}

// round 10
// speedup vs baseline: 1.6952x; 1.6952x over previous
#include <cuda_runtime.h>
#include <cstdint>

// CostVolume1D via cp.async 5-stage smem pipeline.
// out[n,d,h,w] = (1/C) * sum_c f1[n,c,h,w] * f2pad[n,c,h,w+d-4]
// One CTA per (n,h) row; TPB=160 (one float4 of w per thread).
// Per channel: 2 cp.async(16B)/thread (f1 row + f2 row into smem with 16B halo),
// depth-4 in flight; compute = 4 LDS.128 + 36 FFMA per thread.

#define Nn     4
#define Cc     128
#define Hh     192
#define Ww     640
#define NS     9
#define TPB    160
#define VW     160                       // float4 per row
#define STAGES 5
#define S1B    (VW * 16)                 // 2560 B  (f1 row)
#define S2B    ((Ww + 8) * 4)            // 2592 B  (f2 row + 4+4 float halo)
#define SLOTB  (S1B + S2B)               // 5152 B per stage

__device__ __forceinline__ void cp_async16(uint32_t dst, const void* src) {
    asm volatile("cp.async.cg.shared.global [%0], [%1], 16;\n" :: "r"(dst), "l"(src));
}
__device__ __forceinline__ void cp_commit() {
    asm volatile("cp.async.commit_group;\n");
}
__device__ __forceinline__ void cp_wait3() {
    asm volatile("cp.async.wait_group 3;\n");
}

__global__ __launch_bounds__(TPB)
void costvol1d_kernel(const float4* __restrict__ f1,
                      const float4* __restrict__ f2,
                      float* __restrict__ out)
{
    __shared__ __align__(16) char smem[STAGES * SLOTB];

    const int tid = threadIdx.x;            // 0..159, also the float4 index v
    const int bx  = blockIdx.x;             // n*Hh + h
    const int n   = bx / Hh;
    const int h   = bx % Hh;

    uint32_t sbase;
    asm("{ .reg .u64 t; cvta.to.shared.u64 t, %1; cvt.u32.u64 %0, t; }"
        : "=r"(sbase) : "l"(smem));

    // Zero the 16B halos (front+back) of every stage's f2 row. Never
    // overwritten by cp.async (which writes [16, 16+2560) of the f2 region).
    if (tid < STAGES * 2) {
        const int s    = tid >> 1;
        const int back = tid & 1;
        float4* p = (float4*)(smem + s * SLOTB + S1B + (back ? (S2B - 16) : 0));
        *p = make_float4(0.f, 0.f, 0.f, 0.f);
    }

    // Row base (in float4 units) for channel c is rb + c*Hh*VW.
    const size_t rb = ((size_t)n * Cc * Hh + h) * VW;

    // Prologue: stage channels 0..3 into slots 0..3.
    #pragma unroll
    for (int s = 0; s < STAGES - 1; s++) {
        const float4* src1 = f1 + rb + (size_t)s * (Hh * VW) + tid;
        const float4* src2 = f2 + rb + (size_t)s * (Hh * VW) + tid;
        cp_async16(sbase + s * SLOTB + tid * 16, src1);
        cp_async16(sbase + s * SLOTB + S1B + 16 + tid * 16, src2);
        cp_commit();
    }

    float acc[NS * 4];
    #pragma unroll
    for (int i = 0; i < NS * 4; i++) acc[i] = 0.0f;

    int slot = 0;        // slot of channel c
    int islot = STAGES - 1; // slot for channel c+4

    for (int c = 0; c < Cc; c++) {
        cp_wait3();          // group for channel c complete (this thread)
        __syncthreads();     // all threads' copies of slot visible; prior
                             // readers of islot's old contents are done.

        const float4* s1p = (const float4*)(smem + slot * SLOTB);
        const float4* s2p = (const float4*)(smem + slot * SLOTB + S1B);

        const float4 a  = s1p[tid];
        const float4 wa = s2p[tid];       // f2pad[4v-4 .. 4v-1]
        const float4 wb = s2p[tid + 1];   // f2pad[4v   .. 4v+3]
        const float4 wc = s2p[tid + 2];   // f2pad[4v+4 .. 4v+7]

        float win[12];
        win[0] = wa.x; win[1] = wa.y; win[2]  = wa.z; win[3]  = wa.w;
        win[4] = wb.x; win[5] = wb.y; win[6]  = wb.z; win[7]  = wb.w;
        win[8] = wc.x; win[9] = wc.y; win[10] = wc.z; win[11] = wc.w;

        float av[4];
        av[0] = a.x; av[1] = a.y; av[2] = a.z; av[3] = a.w;

        #pragma unroll
        for (int d = 0; d < NS; d++) {
            #pragma unroll
            for (int j = 0; j < 4; j++) {
                acc[d * 4 + j] = fmaf(av[j], win[j + d], acc[d * 4 + j]);
            }
        }

        // Refill islot with channel c+4 (its previous contents, channel c-1,
        // were fully consumed before the barrier above). Always commit so the
        // pending-group count stays uniform for cp_wait3.
        const int cn = c + STAGES - 1;
        if (cn < Cc) {
            const float4* src1 = f1 + rb + (size_t)cn * (Hh * VW) + tid;
            const float4* src2 = f2 + rb + (size_t)cn * (Hh * VW) + tid;
            cp_async16(sbase + islot * SLOTB + tid * 16, src1);
            cp_async16(sbase + islot * SLOTB + S1B + 16 + tid * 16, src2);
        }
        cp_commit();

        slot  = (slot  == STAGES - 1) ? 0 : slot + 1;
        islot = (islot == STAGES - 1) ? 0 : islot + 1;
    }

    // Epilogue: channel mean, float4 stores. out[n][d][h][4v .. 4v+3]
    const float inv = 1.0f / (float)Cc;
    float4* o4 = (float4*)out;
    #pragma unroll
    for (int d = 0; d < NS; d++) {
        float4 o;
        o.x = acc[d * 4 + 0] * inv;
        o.y = acc[d * 4 + 1] * inv;
        o.z = acc[d * 4 + 2] * inv;
        o.w = acc[d * 4 + 3] * inv;
        o4[((size_t)(n * NS + d) * Hh + h) * VW + tid] = o;
    }
}

extern "C" void kernel_launch(void* const* d_in, const int* in_sizes, int n_in,
                              void* d_out, int out_size)
{
    const float4* f1 = (const float4*)d_in[0];
    const float4* f2 = (const float4*)d_in[1];
    float* out = (float*)d_out;
    (void)in_sizes; (void)n_in; (void)out_size;

    dim3 grid(Nn * Hh);   // 768 CTAs, one per (n,h) row
    dim3 block(TPB);      // 160 threads
    costvol1d_kernel<<<grid, block>>>(f1, f2, out);
}